// round 12
// baseline (speedup 1.0000x reference)
#include <cuda_runtime.h>
#include <math.h>

#define V 50257
#define H 1024
#define E 1024
#define L 512
#define HE 2048
#define G3 3072
#define NLU 6283          // logits units of 8 rows: ceil(V/8)
#define PF_ROWS 24576     // out_w rows prefetched into L2 (~96 MB)

// ---------------- scratch (no allocations allowed) ----------------
__device__ float g_attn_logits[L];
__device__ float g_att_part[16 * H];
__device__ float g_x[E];
__device__ float g_gi[G3];
__device__ float g_gh[G3];
__device__ float g_h[H];
__device__ float g_logits[V];
__device__ float g_pmax[NLU];
__device__ float g_psum[NLU];
__device__ float g_red[2];
__device__ float g_sink;                 // prefetch discard (never actually written)
__device__ unsigned g_cnt[8];            // barrier arrival counters (self-resetting)
__device__ volatile unsigned g_gate[8];  // barrier release gates (reset by last block)
__device__ unsigned g_done;

__device__ __forceinline__ float warp_sum(float v) {
    #pragma unroll
    for (int o = 16; o; o >>= 1) v += __shfl_down_sync(0xffffffffu, v, o);
    return v;
}
__device__ __forceinline__ float warp_max(float v) {
    #pragma unroll
    for (int o = 16; o; o >>= 1) v = fmaxf(v, __shfl_down_sync(0xffffffffu, v, o));
    return v;
}
__device__ __forceinline__ float blk_sum(float v, float* s) {
    int lane = threadIdx.x & 31, w = threadIdx.x >> 5;
    v = warp_sum(v);
    if (lane == 0) s[w] = v;
    __syncthreads();
    v = (threadIdx.x < 8) ? s[threadIdx.x] : 0.0f;
    if (w == 0) v = warp_sum(v);
    __syncthreads();
    return v;
}
__device__ __forceinline__ float blk_max(float v, float* s) {
    int lane = threadIdx.x & 31, w = threadIdx.x >> 5;
    v = warp_max(v);
    if (lane == 0) s[w] = v;
    __syncthreads();
    v = (threadIdx.x < 8) ? s[threadIdx.x] : -INFINITY;
    if (w == 0) v = warp_max(v);
    __syncthreads();
    return v;
}
__device__ __forceinline__ float sigmoidf_(float x) { return 1.0f / (1.0f + expf(-x)); }

#define DOT4(a, b) ((a).x * (b).x + (a).y * (b).y + (a).z * (b).z + (a).w * (b).w)

// Grid barrier over NC compute blocks. Replay-safe: counter reset by releaser,
// gates reset by last block at kernel end.
__device__ __forceinline__ void gsync(int b, unsigned NC_) {
    __syncthreads();
    if (threadIdx.x == 0) {
        __threadfence();
        unsigned t = atomicAdd(&g_cnt[b], 1u);
        if (t == NC_ - 1u) {
            g_cnt[b] = 0u;            // nobody increments this barrier again this launch
            __threadfence();
            g_gate[b] = 1u;
        } else {
            while (g_gate[b] == 0u) __nanosleep(64);
        }
        __threadfence();
    }
    __syncthreads();
}

__global__ void __launch_bounds__(256, 4)
k_mega(const int* __restrict__ tok, const float* __restrict__ hidden,
       const float* __restrict__ enc, const float* __restrict__ embedding,
       const float* __restrict__ attn_w, const float* __restrict__ attn_b,
       const float* __restrict__ comb_w, const float* __restrict__ comb_b,
       const float* __restrict__ w_ih, const float* __restrict__ w_hh,
       const float* __restrict__ b_ih, const float* __restrict__ b_hh,
       const float* __restrict__ out_w, const float* __restrict__ out_b,
       float* __restrict__ out, int NB)
{
    const int NPF = NB >> 2;          // prefetch blocks
    const unsigned NC = (unsigned)(NB - NPF);  // compute blocks (participate in barriers)
    const int bid = blockIdx.x;
    const int tid = threadIdx.x, warp = tid >> 5, lane = tid & 31;

    __shared__ float4 sx4[512];       // 8 KB, reused across phases
    __shared__ float  sred[32];
    __shared__ float  slog[8];
    __shared__ float  awv[32];
    __shared__ float  sv0, sv1;

    // ======== PREFETCH ROLE: stream first 96 MB of out_w into L2, then exit ========
    if (bid >= (int)NC) {
        const int p = bid - (int)NC;
        const float4* s4 = (const float4*)out_w;
        float4 acc = make_float4(0.f, 0.f, 0.f, 0.f);
        #pragma unroll 4
        for (int r = p; r < PF_ROWS; r += NPF) {
            float4 t = s4[(size_t)r * 256 + tid];
            acc.x += t.x; acc.y += t.y; acc.z += t.z; acc.w += t.w;
        }
        if (acc.x == 1.0e38f && acc.y == -1.0e38f && acc.z == 1.0e37f) g_sink = acc.w;
        return;
    }

    // ======== P1: attn logits (units 0..63) + gh = h0@w_hh.T (units 64..447) ========
    {
        const float* emb = embedding + (size_t)tok[0] * E;
        sx4[tid]       = *(const float4*)(emb + tid * 4);
        sx4[tid + 256] = *(const float4*)(hidden + tid * 4);
    }
    __syncthreads();
    for (int u = bid; u < 448; u += (int)NC) {
        if (u < 64) {
            const int row = u * 8 + warp;
            const float4* wr = (const float4*)(attn_w + (size_t)row * HE);
            float4 w[8];
            float acc = 0.0f;
            #pragma unroll
            for (int k = 0; k < 8; k++) w[k] = wr[lane + 32 * k];
            #pragma unroll
            for (int k = 0; k < 8; k++) acc += DOT4(w[k], sx4[lane + 32 * k]);
            #pragma unroll
            for (int k = 0; k < 8; k++) w[k] = wr[256 + lane + 32 * k];
            #pragma unroll
            for (int k = 0; k < 8; k++) acc += DOT4(w[k], sx4[256 + lane + 32 * k]);
            acc = warp_sum(acc);
            if (lane == 0) g_attn_logits[row] = acc + attn_b[row];
        } else {
            const int row = (u - 64) * 8 + warp;
            const float4* wr = (const float4*)(w_hh + (size_t)row * H);
            float4 w[8];
            float acc = 0.0f;
            #pragma unroll
            for (int k = 0; k < 8; k++) w[k] = wr[lane + 32 * k];
            #pragma unroll
            for (int k = 0; k < 8; k++) acc += DOT4(w[k], sx4[256 + lane + 32 * k]);
            acc = warp_sum(acc);
            if (lane == 0) g_gh[row] = acc + b_hh[row];
        }
    }
    gsync(0, NC);

    // ======== P2: softmax (redundant per block) + attn-apply partials (64 units) ========
    if (bid < 64) {
        float* sl = (float*)sx4;     // 512 floats
        sl[tid]       = g_attn_logits[tid];
        sl[tid + 256] = g_attn_logits[tid + 256];
        __syncthreads();
        float m = fmaxf(sl[tid], sl[tid + 256]);
        m = blk_max(m, sred);
        if (tid == 0) sv0 = m;
        __syncthreads();
        float e = expf(sl[tid] - sv0) + expf(sl[tid + 256] - sv0);
        float s = blk_sum(e, sred);
        if (tid == 0) sv1 = s;
        __syncthreads();
        const int xb = bid & 3, y = bid >> 2;
        const int r0 = y * 32;
        if (tid < 32) {
            float wv = expf(sl[r0 + tid] - sv0) / sv1;
            awv[tid] = wv;
            if (xb == 0) out[V + H + r0 + tid] = wv;    // attn_weights output
        }
        __syncthreads();
        const int col = xb * 256 + tid;
        float acc = 0.0f;
        #pragma unroll 8
        for (int l = 0; l < 32; l++) acc += awv[l] * enc[(size_t)(r0 + l) * H + col];
        g_att_part[y * H + col] = acc;
    }
    gsync(1, NC);

    // ======== P3: x = relu([emb, att] @ comb_w.T + b), 128 units warp-per-row ========
    if (bid < 128) {
        {
            const float* emb = embedding + (size_t)tok[0] * E;
            sx4[tid] = *(const float4*)(emb + tid * 4);
            float4 a = make_float4(0.f, 0.f, 0.f, 0.f);
            #pragma unroll
            for (int p2 = 0; p2 < 16; p2++) {
                float4 t = *(const float4*)(&g_att_part[p2 * H + tid * 4]);
                a.x += t.x; a.y += t.y; a.z += t.z; a.w += t.w;
            }
            sx4[tid + 256] = a;
        }
        __syncthreads();
        const int row = bid * 8 + warp;
        const float4* wr = (const float4*)(comb_w + (size_t)row * HE);
        float4 w[8];
        float acc = 0.0f;
        #pragma unroll
        for (int k = 0; k < 8; k++) w[k] = wr[lane + 32 * k];
        #pragma unroll
        for (int k = 0; k < 8; k++) acc += DOT4(w[k], sx4[lane + 32 * k]);
        #pragma unroll
        for (int k = 0; k < 8; k++) w[k] = wr[256 + lane + 32 * k];
        #pragma unroll
        for (int k = 0; k < 8; k++) acc += DOT4(w[k], sx4[256 + lane + 32 * k]);
        acc = warp_sum(acc);
        if (lane == 0) g_x[row] = fmaxf(acc + comb_b[row], 0.0f);
    }
    gsync(2, NC);

    // ======== P4: gi = x @ w_ih.T + b_ih, 384 units warp-per-row ========
    if (bid < 384) {
        sx4[tid] = *(const float4*)(&g_x[tid * 4]);
        __syncthreads();
        const int row = bid * 8 + warp;
        const float4* wr = (const float4*)(w_ih + (size_t)row * H);
        float4 w[8];
        float acc = 0.0f;
        #pragma unroll
        for (int k = 0; k < 8; k++) w[k] = wr[lane + 32 * k];
        #pragma unroll
        for (int k = 0; k < 8; k++) acc += DOT4(w[k], sx4[lane + 32 * k]);
        acc = warp_sum(acc);
        if (lane == 0) g_gi[row] = acc + b_ih[row];
    }
    gsync(3, NC);

    // ======== P5: GRU gate combine -> h_new ========
    if (bid < 4) {
        const int j = bid * 256 + tid;
        float r = sigmoidf_(g_gi[j]         + g_gh[j]);
        float z = sigmoidf_(g_gi[H + j]     + g_gh[H + j]);
        float n = tanhf(g_gi[2 * H + j] + r * g_gh[2 * H + j]);
        float h = (1.0f - z) * n + z * hidden[j];
        g_h[j]   = h;
        out[V + j] = h;                                  // h_new output
    }
    gsync(4, NC);

    // ======== P6: logits (NLU units of 8 rows) + per-unit LSE partials ========
    sx4[tid] = *(const float4*)(&g_h[tid * 4]);
    __syncthreads();
    for (int u = bid; u < NLU; u += (int)NC) {
        const int row = u * 8 + warp;
        const int cr = (row < V) ? row : V - 1;
        const float4* wr = (const float4*)(out_w + (size_t)cr * H);
        float4 w[8];
        float acc = 0.0f;
        #pragma unroll
        for (int k = 0; k < 8; k++) w[k] = wr[lane + 32 * k];
        #pragma unroll
        for (int k = 0; k < 8; k++) acc += DOT4(w[k], sx4[lane + 32 * k]);
        acc = warp_sum(acc);
        if (lane == 0) {
            float lg = (row < V) ? acc + out_b[row] : -INFINITY;
            if (row < V) g_logits[row] = lg;
            slog[warp] = lg;
        }
        __syncthreads();
        if (warp == 0) {
            float v = (lane < 8) ? slog[lane] : -INFINITY;
            float m = warp_max(v);
            m = __shfl_sync(0xffffffffu, m, 0);
            float e = (lane < 8) ? expf(slog[lane] - m) : 0.0f;
            float s = warp_sum(e);
            if (lane == 0) { g_pmax[u] = m; g_psum[u] = s; }
        }
        __syncthreads();     // slog reused next unit
    }
    gsync(5, NC);

    // ======== P7: combine NLU partials (block 0) ========
    if (bid == 0) {
        float m = -INFINITY;
        for (int i = tid; i < NLU; i += 256) m = fmaxf(m, g_pmax[i]);
        m = blk_max(m, sred);
        if (tid == 0) sv0 = m;
        __syncthreads();
        float s = 0.0f;
        for (int i = tid; i < NLU; i += 256) s += g_psum[i] * expf(g_pmax[i] - sv0);
        s = blk_sum(s, sred);
        if (tid == 0) { g_red[0] = sv0; g_red[1] = logf(s); }
    }
    gsync(6, NC);

    // ======== P8: final log-softmax write ========
    {
        const float M = g_red[0], LSE = g_red[1];
        for (int i = bid * 256 + tid; i < V; i += (int)NC * 256)
            out[i] = g_logits[i] - M - LSE;
    }

    // ======== replay-safe cleanup: last compute block resets gates ========
    __syncthreads();
    if (tid == 0) {
        __threadfence();
        unsigned t = atomicAdd(&g_done, 1u);
        if (t == NC - 1u) {
            #pragma unroll
            for (int i = 0; i < 8; i++) g_gate[i] = 0u;
            g_done = 0u;
            __threadfence();
        }
    }
}

// ---------------- launch ----------------
extern "C" void kernel_launch(void* const* d_in, const int* in_sizes, int n_in,
                              void* d_out, int out_size) {
    const int*   tok       = (const int*)  d_in[0];
    const float* hidden    = (const float*)d_in[1];
    const float* enc       = (const float*)d_in[2];
    const float* embedding = (const float*)d_in[3];
    const float* attn_w    = (const float*)d_in[4];
    const float* attn_b    = (const float*)d_in[5];
    const float* comb_w    = (const float*)d_in[6];
    const float* comb_b    = (const float*)d_in[7];
    const float* w_ih      = (const float*)d_in[8];
    const float* w_hh      = (const float*)d_in[9];
    const float* b_ih      = (const float*)d_in[10];
    const float* b_hh      = (const float*)d_in[11];
    const float* out_w     = (const float*)d_in[12];
    const float* out_b     = (const float*)d_in[13];
    float* out = (float*)d_out;

    // Grid sized to guaranteed co-residency (required by the software grid barrier).
    int dev = 0;
    cudaGetDevice(&dev);
    int sms = 148;
    cudaDeviceGetAttribute(&sms, cudaDevAttrMultiProcessorCount, dev);
    int occ = 0;
    cudaOccupancyMaxActiveBlocksPerMultiprocessor(&occ, k_mega, 256, 0);
    if (occ < 1) occ = 1;
    if (occ > 8) occ = 8;
    int NB = sms * occ;
    if (NB < 592 && occ >= 4) NB = sms * occ;   // (no-op guard; NB derived above)

    // output layout: [log_softmax (V)] [h_new (H)] [attn_weights (L)]
    k_mega<<<NB, 256>>>(tok, hidden, enc, embedding, attn_w, attn_b,
                        comb_w, comb_b, w_ih, w_hh, b_ih, b_hh,
                        out_w, out_b, out, NB);
}

// round 13
// speedup vs baseline: 1.1066x; 1.1066x over previous
#include <cuda_runtime.h>
#include <math.h>

#define V 50257
#define H 1024
#define E 1024
#define L 512
#define HE 2048
#define G3 3072
#define MAXNB 1184

// ---------------- scratch (no allocations allowed) ----------------
__device__ float g_attn_logits[L];
__device__ float g_att_part[16 * H];
__device__ float g_x[E];
__device__ float g_gi[G3];
__device__ float g_gh[G3];
__device__ float g_h[H];
__device__ float g_logits[V];
__device__ float g_pmax[MAXNB];
__device__ float g_psum[MAXNB];
__device__ float g_red[2];
__device__ unsigned g_cnt[8];            // barrier arrival counters (self-resetting)
__device__ volatile unsigned g_gate[8];  // barrier release gates (reset at end)
__device__ unsigned g_done;

__device__ __forceinline__ float warp_sum(float v) {
    #pragma unroll
    for (int o = 16; o; o >>= 1) v += __shfl_down_sync(0xffffffffu, v, o);
    return v;
}
__device__ __forceinline__ float warp_max(float v) {
    #pragma unroll
    for (int o = 16; o; o >>= 1) v = fmaxf(v, __shfl_down_sync(0xffffffffu, v, o));
    return v;
}
__device__ __forceinline__ float blk_sum(float v, float* s) {
    int lane = threadIdx.x & 31, w = threadIdx.x >> 5;
    v = warp_sum(v);
    if (lane == 0) s[w] = v;
    __syncthreads();
    v = (threadIdx.x < 8) ? s[threadIdx.x] : 0.0f;
    if (w == 0) v = warp_sum(v);
    __syncthreads();
    return v;
}
__device__ __forceinline__ float blk_max(float v, float* s) {
    int lane = threadIdx.x & 31, w = threadIdx.x >> 5;
    v = warp_max(v);
    if (lane == 0) s[w] = v;
    __syncthreads();
    v = (threadIdx.x < 8) ? s[threadIdx.x] : -INFINITY;
    if (w == 0) v = warp_max(v);
    __syncthreads();
    return v;
}
__device__ __forceinline__ float sigmoidf_(float x) { return 1.0f / (1.0f + expf(-x)); }

#define DOT4(a, b) ((a).x * (b).x + (a).y * (b).y + (a).z * (b).z + (a).w * (b).w)

// Grid barrier over NC blocks. Counter reset by releaser; gates reset at kernel end.
__device__ __forceinline__ void gsync(int b, unsigned NC_) {
    __syncthreads();
    if (threadIdx.x == 0) {
        __threadfence();
        unsigned t = atomicAdd(&g_cnt[b], 1u);
        if (t == NC_ - 1u) {
            g_cnt[b] = 0u;
            __threadfence();
            g_gate[b] = 1u;
        } else {
            while (g_gate[b] == 0u) __nanosleep(64);
        }
        __threadfence();
    }
    __syncthreads();
}

__global__ void __launch_bounds__(256, 4)
k_mega(const int* __restrict__ tok, const float* __restrict__ hidden,
       const float* __restrict__ enc, const float* __restrict__ embedding,
       const float* __restrict__ attn_w, const float* __restrict__ attn_b,
       const float* __restrict__ comb_w, const float* __restrict__ comb_b,
       const float* __restrict__ w_ih, const float* __restrict__ w_hh,
       const float* __restrict__ b_ih, const float* __restrict__ b_hh,
       const float* __restrict__ out_w, const float* __restrict__ out_b,
       float* __restrict__ out, int NB)
{
    const unsigned NC = (unsigned)NB;
    const int bid = blockIdx.x;
    const int tid = threadIdx.x, warp = tid >> 5, lane = tid & 31;

    __shared__ float4 sx4[512];       // 8 KB, reused across phases
    __shared__ float  sred[32];
    __shared__ float  sm8[8], ss8[8];
    __shared__ float  awv[32];
    __shared__ float  sv0, sv1;

    // ======== P1: attn logits (units 0..63) + gh = h0@w_hh.T (units 64..447) ========
    {
        const float* emb = embedding + (size_t)tok[0] * E;
        sx4[tid]       = *(const float4*)(emb + tid * 4);
        sx4[tid + 256] = *(const float4*)(hidden + tid * 4);
    }
    __syncthreads();
    for (int u = bid; u < 448; u += (int)NC) {
        if (u < 64) {
            const int row = u * 8 + warp;
            const float4* wr = (const float4*)(attn_w + (size_t)row * HE);
            float4 w[8];
            float acc = 0.0f;
            #pragma unroll
            for (int k = 0; k < 8; k++) w[k] = wr[lane + 32 * k];
            #pragma unroll
            for (int k = 0; k < 8; k++) acc += DOT4(w[k], sx4[lane + 32 * k]);
            #pragma unroll
            for (int k = 0; k < 8; k++) w[k] = wr[256 + lane + 32 * k];
            #pragma unroll
            for (int k = 0; k < 8; k++) acc += DOT4(w[k], sx4[256 + lane + 32 * k]);
            acc = warp_sum(acc);
            if (lane == 0) g_attn_logits[row] = acc + attn_b[row];
        } else {
            const int row = (u - 64) * 8 + warp;
            const float4* wr = (const float4*)(w_hh + (size_t)row * H);
            float4 w[8];
            float acc = 0.0f;
            #pragma unroll
            for (int k = 0; k < 8; k++) w[k] = wr[lane + 32 * k];
            #pragma unroll
            for (int k = 0; k < 8; k++) acc += DOT4(w[k], sx4[256 + lane + 32 * k]);
            acc = warp_sum(acc);
            if (lane == 0) g_gh[row] = acc + b_hh[row];
        }
    }
    gsync(0, NC);

    // ======== P2: softmax (redundant per block) + attn-apply partials (64 units) ========
    if (bid < 64) {
        float* sl = (float*)sx4;     // 512 floats
        sl[tid]       = g_attn_logits[tid];
        sl[tid + 256] = g_attn_logits[tid + 256];
        __syncthreads();
        float m = fmaxf(sl[tid], sl[tid + 256]);
        m = blk_max(m, sred);
        if (tid == 0) sv0 = m;
        __syncthreads();
        float e = expf(sl[tid] - sv0) + expf(sl[tid + 256] - sv0);
        float s = blk_sum(e, sred);
        if (tid == 0) sv1 = s;
        __syncthreads();
        const int xb = bid & 3, y = bid >> 2;
        const int r0 = y * 32;
        if (tid < 32) {
            float wv = expf(sl[r0 + tid] - sv0) / sv1;
            awv[tid] = wv;
            if (xb == 0) out[V + H + r0 + tid] = wv;    // attn_weights output
        }
        __syncthreads();
        const int col = xb * 256 + tid;
        float acc = 0.0f;
        #pragma unroll 8
        for (int l = 0; l < 32; l++) acc += awv[l] * enc[(size_t)(r0 + l) * H + col];
        g_att_part[y * H + col] = acc;
    }
    gsync(1, NC);

    // ======== P3: x = relu([emb, att] @ comb_w.T + b), 128 units warp-per-row ========
    if (bid < 128) {
        {
            const float* emb = embedding + (size_t)tok[0] * E;
            sx4[tid] = *(const float4*)(emb + tid * 4);
            float4 a = make_float4(0.f, 0.f, 0.f, 0.f);
            #pragma unroll
            for (int p2 = 0; p2 < 16; p2++) {
                float4 t = *(const float4*)(&g_att_part[p2 * H + tid * 4]);
                a.x += t.x; a.y += t.y; a.z += t.z; a.w += t.w;
            }
            sx4[tid + 256] = a;
        }
        __syncthreads();
        const int row = bid * 8 + warp;
        const float4* wr = (const float4*)(comb_w + (size_t)row * HE);
        float4 w[8];
        float acc = 0.0f;
        #pragma unroll
        for (int k = 0; k < 8; k++) w[k] = wr[lane + 32 * k];
        #pragma unroll
        for (int k = 0; k < 8; k++) acc += DOT4(w[k], sx4[lane + 32 * k]);
        #pragma unroll
        for (int k = 0; k < 8; k++) w[k] = wr[256 + lane + 32 * k];
        #pragma unroll
        for (int k = 0; k < 8; k++) acc += DOT4(w[k], sx4[256 + lane + 32 * k]);
        acc = warp_sum(acc);
        if (lane == 0) g_x[row] = fmaxf(acc + comb_b[row], 0.0f);
    }
    gsync(2, NC);

    // ======== P4: gi = x @ w_ih.T + b_ih, 384 units warp-per-row ========
    if (bid < 384) {
        sx4[tid] = *(const float4*)(&g_x[tid * 4]);
        __syncthreads();
        const int row = bid * 8 + warp;
        const float4* wr = (const float4*)(w_ih + (size_t)row * H);
        float4 w[8];
        float acc = 0.0f;
        #pragma unroll
        for (int k = 0; k < 8; k++) w[k] = wr[lane + 32 * k];
        #pragma unroll
        for (int k = 0; k < 8; k++) acc += DOT4(w[k], sx4[lane + 32 * k]);
        acc = warp_sum(acc);
        if (lane == 0) g_gi[row] = acc + b_ih[row];
    }
    gsync(3, NC);

    // ======== P5: GRU gate combine -> h_new ========
    if (bid < 4) {
        const int j = bid * 256 + tid;
        float r = sigmoidf_(g_gi[j]         + g_gh[j]);
        float z = sigmoidf_(g_gi[H + j]     + g_gh[H + j]);
        float n = tanhf(g_gi[2 * H + j] + r * g_gh[2 * H + j]);
        float h = (1.0f - z) * n + z * hidden[j];
        g_h[j]   = h;
        out[V + j] = h;                                  // h_new output
    }
    gsync(4, NC);

    // ======== P6: logits row-per-warp grid-stride + ONLINE per-warp LSE ========
    sx4[tid] = *(const float4*)(&g_h[tid * 4]);
    __syncthreads();
    {
        const int gw = bid * 8 + warp;           // global warp id
        const int TW = (int)NC * 8;              // total warps
        float lm = -INFINITY, ls = 0.0f;         // lane-0 online (max, sumexp)
        for (int row = gw; row < V; row += TW) {
            const float4* wr = (const float4*)(out_w + (size_t)row * H);
            float4 w[8];
            float acc = 0.0f;
            #pragma unroll
            for (int k = 0; k < 8; k++) w[k] = wr[lane + 32 * k];
            #pragma unroll
            for (int k = 0; k < 8; k++) acc += DOT4(w[k], sx4[lane + 32 * k]);
            acc = warp_sum(acc);
            if (lane == 0) {
                float lg = acc + out_b[row];
                g_logits[row] = lg;
                float nm = fmaxf(lm, lg);
                ls = ls * expf(lm - nm) + expf(lg - nm);
                lm = nm;
            }
        }
        if (lane == 0) { sm8[warp] = lm; ss8[warp] = ls; }
        __syncthreads();
        if (warp == 0) {       // combine 8 warp partials -> block partial
            float m = (lane < 8) ? sm8[lane] : -INFINITY;
            float M = warp_max(m);
            M = __shfl_sync(0xffffffffu, M, 0);
            float s = (lane < 8) ? ss8[lane] * expf(sm8[lane] - M) : 0.0f;
            s = warp_sum(s);
            if (lane == 0) { g_pmax[bid] = M; g_psum[bid] = s; }
        }
    }
    gsync(5, NC);

    // ======== P7: combine NB partials (block 0) ========
    if (bid == 0) {
        float m = -INFINITY;
        for (int i = tid; i < NB; i += 256) m = fmaxf(m, g_pmax[i]);
        m = blk_max(m, sred);
        if (tid == 0) sv0 = m;
        __syncthreads();
        float s = 0.0f;
        for (int i = tid; i < NB; i += 256) s += g_psum[i] * expf(g_pmax[i] - sv0);
        s = blk_sum(s, sred);
        if (tid == 0) { g_red[0] = sv0; g_red[1] = logf(s); }
    }
    gsync(6, NC);

    // ======== P8: final log-softmax write (logits hot in L2) ========
    {
        const float M = g_red[0], LSE = g_red[1];
        for (int i = bid * 256 + tid; i < V; i += (int)NC * 256)
            out[i] = g_logits[i] - M - LSE;
    }

    // ======== replay-safe cleanup: last block resets gates ========
    __syncthreads();
    if (tid == 0) {
        __threadfence();
        unsigned t = atomicAdd(&g_done, 1u);
        if (t == NC - 1u) {
            #pragma unroll
            for (int i = 0; i < 8; i++) g_gate[i] = 0u;
            g_done = 0u;
            __threadfence();
        }
    }
}

// ---------------- launch ----------------
extern "C" void kernel_launch(void* const* d_in, const int* in_sizes, int n_in,
                              void* d_out, int out_size) {
    const int*   tok       = (const int*)  d_in[0];
    const float* hidden    = (const float*)d_in[1];
    const float* enc       = (const float*)d_in[2];
    const float* embedding = (const float*)d_in[3];
    const float* attn_w    = (const float*)d_in[4];
    const float* attn_b    = (const float*)d_in[5];
    const float* comb_w    = (const float*)d_in[6];
    const float* comb_b    = (const float*)d_in[7];
    const float* w_ih      = (const float*)d_in[8];
    const float* w_hh      = (const float*)d_in[9];
    const float* b_ih      = (const float*)d_in[10];
    const float* b_hh      = (const float*)d_in[11];
    const float* out_w     = (const float*)d_in[12];
    const float* out_b     = (const float*)d_in[13];
    float* out = (float*)d_out;

    // Grid sized to guaranteed co-residency (required by the software grid barrier).
    int dev = 0;
    cudaGetDevice(&dev);
    int sms = 148;
    cudaDeviceGetAttribute(&sms, cudaDevAttrMultiProcessorCount, dev);
    int occ = 0;
    cudaOccupancyMaxActiveBlocksPerMultiprocessor(&occ, k_mega, 256, 0);
    if (occ < 1) occ = 1;
    if (occ > 8) occ = 8;
    int NB = sms * occ;
    if (NB > MAXNB) NB = MAXNB;

    // output layout: [log_softmax (V)] [h_new (H)] [attn_weights (L)]
    k_mega<<<NB, 256>>>(tok, hidden, enc, embedding, attn_w, attn_b,
                        comb_w, comb_b, w_ih, w_hh, b_ih, b_hh,
                        out_w, out_b, out, NB);
}

// round 14
// speedup vs baseline: 1.1402x; 1.0303x over previous
#include <cuda_runtime.h>
#include <math.h>
#include <stdint.h>

#define V 50257
#define H 1024
#define E 1024
#define L 512
#define HE 2048
#define G3 3072
#define NP 16            // L-partitions for attn-apply (32 rows each)
#define RPB 64           // logits rows per block
#define NLB ((V + RPB - 1) / RPB)   // 786 logits blocks
#define PIPE_SMEM (3 * 2048 * 16)   // 3 stages x 8 rows x 4KB = 96KB

// ---------------- scratch (no allocations allowed) ----------------
__device__ float g_attn_logits[L];
__device__ float g_att_part[NP * H];
__device__ float g_x[E];
__device__ float g_gi[G3];
__device__ float g_gh[G3];
__device__ float g_h[H];
__device__ float g_logits[V];
__device__ float g_pmax[64];
__device__ float g_psum[64];

__device__ __forceinline__ float warp_sum(float v) {
    #pragma unroll
    for (int o = 16; o; o >>= 1) v += __shfl_down_sync(0xffffffffu, v, o);
    return v;
}
__device__ __forceinline__ float warp_max(float v) {
    #pragma unroll
    for (int o = 16; o; o >>= 1) v = fmaxf(v, __shfl_down_sync(0xffffffffu, v, o));
    return v;
}
__device__ __forceinline__ float blk_sum(float v, float* s) {
    int lane = threadIdx.x & 31, w = threadIdx.x >> 5;
    v = warp_sum(v);
    if (lane == 0) s[w] = v;
    __syncthreads();
    int nw = (blockDim.x + 31) >> 5;
    v = (threadIdx.x < nw) ? s[threadIdx.x] : 0.0f;
    if (w == 0) v = warp_sum(v);
    __syncthreads();
    return v;
}
__device__ __forceinline__ float blk_max(float v, float* s) {
    int lane = threadIdx.x & 31, w = threadIdx.x >> 5;
    v = warp_max(v);
    if (lane == 0) s[w] = v;
    __syncthreads();
    int nw = (blockDim.x + 31) >> 5;
    v = (threadIdx.x < nw) ? s[threadIdx.x] : -INFINITY;
    if (w == 0) v = warp_max(v);
    __syncthreads();
    return v;
}
__device__ __forceinline__ float sigmoidf_(float x) { return 1.0f / (1.0f + expf(-x)); }

#define DOT4(a, b) ((a).x * (b).x + (a).y * (b).y + (a).z * (b).z + (a).w * (b).w)

__device__ __forceinline__ void cp_async16(uint32_t saddr, const void* gptr) {
    asm volatile("cp.async.cg.shared.global [%0], [%1], 16;" :: "r"(saddr), "l"(gptr));
}
#define CP_COMMIT() asm volatile("cp.async.commit_group;")
#define CP_WAIT1()  asm volatile("cp.async.wait_group 1;")

// ---------------- 1) attention logits: warp-per-row over [emb,h0] (2048) ----------------
__global__ void k_attn(const int* __restrict__ tok, const float* __restrict__ hidden,
                       const float* __restrict__ embedding,
                       const float* __restrict__ attn_w, const float* __restrict__ attn_b) {
    __shared__ float4 sx[HE / 4];
    const int tid = threadIdx.x;
    {
        const float* emb = embedding + (size_t)tok[0] * E;
        sx[tid]       = *(const float4*)(emb + tid * 4);
        sx[tid + 256] = *(const float4*)(hidden + tid * 4);
    }
    __syncthreads();
    const int warp = tid >> 5, lane = tid & 31;
    const int row = blockIdx.x * 8 + warp;
    const float4* wr = (const float4*)(attn_w + (size_t)row * HE);
    float acc = 0.0f;
    float4 w[8];
    #pragma unroll
    for (int k = 0; k < 8; k++) w[k] = wr[lane + 32 * k];
    #pragma unroll
    for (int k = 0; k < 8; k++) { float4 x4 = sx[lane + 32 * k]; acc += DOT4(w[k], x4); }
    #pragma unroll
    for (int k = 0; k < 8; k++) w[k] = wr[256 + lane + 32 * k];
    #pragma unroll
    for (int k = 0; k < 8; k++) { float4 x4 = sx[256 + lane + 32 * k]; acc += DOT4(w[k], x4); }
    acc = warp_sum(acc);
    if (lane == 0) g_attn_logits[row] = acc + attn_b[row];
}

// ---------------- 2) attn partials with FUSED softmax: grid (4, NP) ----------------
__global__ void k_attnapply(const float* __restrict__ enc, float* __restrict__ out_aw) {
    __shared__ float s[32];
    __shared__ float sl[L];
    __shared__ float aw[32];
    __shared__ float bm, bs;
    const int tid = threadIdx.x;
    sl[tid]       = g_attn_logits[tid];
    sl[tid + 256] = g_attn_logits[tid + 256];
    __syncthreads();
    float m = fmaxf(sl[tid], sl[tid + 256]);
    m = blk_max(m, s);
    if (tid == 0) bm = m;
    __syncthreads();
    float e = expf(sl[tid] - bm) + expf(sl[tid + 256] - bm);
    float sum = blk_sum(e, s);
    if (tid == 0) bs = sum;
    __syncthreads();
    const int r0 = blockIdx.y * 32;
    if (tid < 32) {
        float wv = expf(sl[r0 + tid] - bm) / bs;
        aw[tid] = wv;
        if (blockIdx.x == 0) out_aw[r0 + tid] = wv;
    }
    __syncthreads();
    const int col = blockIdx.x * blockDim.x + tid;
    float acc = 0.0f;
    #pragma unroll 8
    for (int l = 0; l < 32; l++) acc += aw[l] * enc[(size_t)(r0 + l) * H + col];
    g_att_part[blockIdx.y * H + col] = acc;
}

// ---------------- 3) x = relu([emb, att] @ comb_w.T + b): warp-per-row ----------------
__global__ void k_comb(const int* __restrict__ tok, const float* __restrict__ embedding,
                       const float* __restrict__ comb_w, const float* __restrict__ comb_b) {
    __shared__ float4 sx[HE / 4];
    const int tid = threadIdx.x;
    {
        const float* emb = embedding + (size_t)tok[0] * E;
        sx[tid] = *(const float4*)(emb + tid * 4);
        float4 a = make_float4(0.f, 0.f, 0.f, 0.f);
        #pragma unroll
        for (int p = 0; p < NP; p++) {
            float4 t = *(const float4*)(&g_att_part[p * H + tid * 4]);
            a.x += t.x; a.y += t.y; a.z += t.z; a.w += t.w;
        }
        sx[tid + 256] = a;
    }
    __syncthreads();
    const int warp = tid >> 5, lane = tid & 31;
    const int row = blockIdx.x * 8 + warp;
    const float4* wr = (const float4*)(comb_w + (size_t)row * HE);
    float acc = 0.0f;
    float4 w[8];
    #pragma unroll
    for (int k = 0; k < 8; k++) w[k] = wr[lane + 32 * k];
    #pragma unroll
    for (int k = 0; k < 8; k++) { float4 x4 = sx[lane + 32 * k]; acc += DOT4(w[k], x4); }
    #pragma unroll
    for (int k = 0; k < 8; k++) w[k] = wr[256 + lane + 32 * k];
    #pragma unroll
    for (int k = 0; k < 8; k++) { float4 x4 = sx[256 + lane + 32 * k]; acc += DOT4(w[k], x4); }
    acc = warp_sum(acc);
    if (lane == 0) g_x[row] = fmaxf(acc + comb_b[row], 0.0f);
}

// ---------------- 4) GRU matvecs: warp-per-row, 16 loads in flight (proven 3.0 TB/s) ------
__global__ void k_gru(const float* __restrict__ w_ih, const float* __restrict__ w_hh,
                      const float* __restrict__ b_ih, const float* __restrict__ b_hh,
                      const float* __restrict__ hidden) {
    __shared__ float4 sxv[H / 4];
    __shared__ float4 shv[H / 4];
    const int tid = threadIdx.x;
    sxv[tid] = *(const float4*)(&g_x[tid * 4]);
    shv[tid] = *(const float4*)(hidden + tid * 4);
    __syncthreads();
    const int warp = tid >> 5, lane = tid & 31;
    const int row = blockIdx.x * 8 + warp;
    const float4* wi = (const float4*)(w_ih + (size_t)row * H);
    const float4* wh = (const float4*)(w_hh + (size_t)row * H);
    float4 a[8], b[8];
    #pragma unroll
    for (int k = 0; k < 8; k++) a[k] = wi[lane + 32 * k];
    #pragma unroll
    for (int k = 0; k < 8; k++) b[k] = wh[lane + 32 * k];
    float ai = 0.0f, ah = 0.0f;
    #pragma unroll
    for (int k = 0; k < 8; k++) {
        float4 x4 = sxv[lane + 32 * k];
        float4 h4 = shv[lane + 32 * k];
        ai += DOT4(a[k], x4);
        ah += DOT4(b[k], h4);
    }
    ai = warp_sum(ai);
    ah = warp_sum(ah);
    if (lane == 0) {
        g_gi[row] = ai + b_ih[row];
        g_gh[row] = ah + b_hh[row];
    }
}

// ---------------- 5) GRU gate combine -> h_new ----------------
__global__ void k_hnew(const float* __restrict__ hidden, float* __restrict__ out_h) {
    const int j = blockIdx.x * blockDim.x + threadIdx.x;
    float r = sigmoidf_(g_gi[j]         + g_gh[j]);
    float z = sigmoidf_(g_gi[H + j]     + g_gh[H + j]);
    float n = tanhf(g_gi[2 * H + j] + r * g_gh[2 * H + j]);
    float h = (1.0f - z) * n + z * hidden[j];
    g_h[j]  = h;
    out_h[j] = h;
}

// ---------------- 6) logits: cp.async 3-stage pipelined streamer ----------------
// Block owns 64 rows; 8 stages of 8 rows (32KB each). Loads stream via cp.async
// decoupled from compute. Always-commit + positional wait_group 1.
__global__ void k_logits_pipe(const float* __restrict__ out_w, const float* __restrict__ out_b) {
    extern __shared__ float4 sbuf[];        // 3 * 2048 float4 = 96KB
    __shared__ float4 shv[256];             // h_new, 4KB
    const int tid = threadIdx.x, warp = tid >> 5, lane = tid & 31;
    shv[tid] = *(const float4*)(&g_h[tid * 4]);
    const int base = blockIdx.x * RPB;
    const uint32_t sb = (uint32_t)__cvta_generic_to_shared(sbuf);

    // stage s -> buffer buf: rows [base+8s, base+8s+8), clamped row source
    #define ISSUE_STAGE(s, buf)                                                     \
        do {                                                                        \
            _Pragma("unroll")                                                       \
            for (int j = 0; j < 8; j++) {                                           \
                int row_ = base + (s) * 8 + j;                                      \
                if (row_ >= V) row_ = V - 1;                                        \
                cp_async16(sb + (uint32_t)(((buf) * 2048 + j * 256 + tid) * 16),    \
                           (const float4*)out_w + (size_t)row_ * 256 + tid);        \
            }                                                                       \
        } while (0)

    ISSUE_STAGE(0, 0); CP_COMMIT();
    ISSUE_STAGE(1, 1); CP_COMMIT();
    __syncthreads();    // shv visible to all warps

    #pragma unroll 1
    for (int s = 0; s < 8; s++) {
        CP_WAIT1();          // all but most recent group done -> stage s resident
        __syncthreads();
        const int buf = s % 3;
        const int row = base + s * 8 + warp;
        const float4* rp = sbuf + buf * 2048 + warp * 256;
        float acc = 0.0f;
        #pragma unroll
        for (int k = 0; k < 8; k++) {
            float4 w4 = rp[lane + 32 * k];
            float4 h4 = shv[lane + 32 * k];
            acc += DOT4(w4, h4);
        }
        acc = warp_sum(acc);
        if (lane == 0 && row < V) g_logits[row] = acc + out_b[row];
        __syncthreads();     // all warps done with buf before it is re-filled
        if (s + 2 < 8) ISSUE_STAGE(s + 2, (s + 2) % 3);
        CP_COMMIT();         // commit every iteration (possibly empty group)
    }
    #undef ISSUE_STAGE
}

// ---------------- 7) partial log-sum-exp: 64 blocks ----------------
#define LSE_CHUNK 786
__global__ void k_lse1() {
    __shared__ float s[32];
    __shared__ float bm;
    const int b = blockIdx.x;
    const int lo = b * LSE_CHUNK;
    const int hi = min(lo + LSE_CHUNK, V);
    float m = -INFINITY;
    for (int v = lo + threadIdx.x; v < hi; v += blockDim.x) m = fmaxf(m, g_logits[v]);
    m = blk_max(m, s);
    if (threadIdx.x == 0) bm = m;
    __syncthreads();
    float m0 = bm;
    float sum = 0.0f;
    for (int v = lo + threadIdx.x; v < hi; v += blockDim.x) sum += expf(g_logits[v] - m0);
    sum = blk_sum(sum, s);
    if (threadIdx.x == 0) {
        g_pmax[b] = m0;
        g_psum[b] = sum;
    }
}

// ---------------- 8) final log-softmax write with FUSED partial combine ----------------
__global__ void k_out(float* __restrict__ out) {
    __shared__ float sm_, sls;
    const int tid = threadIdx.x;
    if (tid < 32) {
        float m = fmaxf(g_pmax[tid], g_pmax[tid + 32]);
        m = warp_max(m);
        m = __shfl_sync(0xffffffffu, m, 0);
        float s2 = g_psum[tid] * expf(g_pmax[tid] - m)
                 + g_psum[tid + 32] * expf(g_pmax[tid + 32] - m);
        s2 = warp_sum(s2);
        if (tid == 0) { sm_ = m; sls = logf(s2); }
    }
    __syncthreads();
    const int v = blockIdx.x * blockDim.x + tid;
    if (v < V) out[v] = g_logits[v] - sm_ - sls;
}

// ---------------- launch ----------------
extern "C" void kernel_launch(void* const* d_in, const int* in_sizes, int n_in,
                              void* d_out, int out_size) {
    const int*   tok       = (const int*)  d_in[0];
    const float* hidden    = (const float*)d_in[1];
    const float* enc       = (const float*)d_in[2];
    const float* embedding = (const float*)d_in[3];
    const float* attn_w    = (const float*)d_in[4];
    const float* attn_b    = (const float*)d_in[5];
    const float* comb_w    = (const float*)d_in[6];
    const float* comb_b    = (const float*)d_in[7];
    const float* w_ih      = (const float*)d_in[8];
    const float* w_hh      = (const float*)d_in[9];
    const float* b_ih      = (const float*)d_in[10];
    const float* b_hh      = (const float*)d_in[11];
    const float* out_w     = (const float*)d_in[12];
    const float* out_b     = (const float*)d_in[13];
    float* out = (float*)d_out;

    // opt-in to 96KB dynamic smem for the pipelined streamer (idempotent, capture-safe)
    static int smem_set = 0;
    if (!smem_set) {
        cudaFuncSetAttribute(k_logits_pipe, cudaFuncAttributeMaxDynamicSharedMemorySize,
                             PIPE_SMEM);
        smem_set = 1;
    }

    // output layout: [log_softmax (V)] [h_new (H)] [attn_weights (L)]
    k_attn       <<<L / 8, 256>>>(tok, hidden, embedding, attn_w, attn_b);
    k_attnapply  <<<dim3(4, NP), 256>>>(enc, out + V + H);
    k_comb       <<<E / 8, 256>>>(tok, embedding, comb_w, comb_b);
    k_gru        <<<G3 / 8, 256>>>(w_ih, w_hh, b_ih, b_hh, hidden);
    k_hnew       <<<H / 256, 256>>>(hidden, out + V);
    k_logits_pipe<<<NLB, 256, PIPE_SMEM>>>(out_w, out_b);
    k_lse1       <<<64, 256>>>();
    k_out        <<<(V + 255) / 256, 256>>>(out);
}